// round 1
// baseline (speedup 1.0000x reference)
#include <cuda_runtime.h>
#include <cuda_bf16.h>
#include <math.h>

// Problem constants
#define BATCH     1024
#define FDIM      1024
#define NCONCEPT  32768
#define INV_T     10.0f   // 1 / 0.1

// ---------------- scratch (device globals; no allocation allowed) ----------
__device__ float g_P[BATCH * FDIM];                      // projected (then normalized)
__device__ float g_S[(size_t)BATCH * NCONCEPT];          // similarities (134 MB)

// ---------------------------------------------------------------------------
// Classic 128x128x16 register-blocked SGEMM, NT layout:
//   C[m,n] = sum_k A[m*K + k] * B[n*K + k]   (+ bias[n] if BIAS)
// 256 threads, 8x8 accumulators per thread in split-quadrant layout.
// Requires M % 128 == 0, N % 128 == 0, K % 16 == 0 (true for all our shapes).
// ---------------------------------------------------------------------------
template <bool BIAS>
__global__ void __launch_bounds__(256, 2)
sgemm128_nt(const float* __restrict__ A,
            const float* __restrict__ B,
            const float* __restrict__ bias,
            float* __restrict__ C,
            int M, int N, int K)
{
    __shared__ __align__(16) float As[16][132];
    __shared__ __align__(16) float Bs[16][132];

    const int tid = threadIdx.x;
    const int bm  = blockIdx.y * 128;
    const int bn  = blockIdx.x * 128;

    // global-load mapping: each thread loads 2 float4 from A and 2 from B
    const int lr = tid >> 2;            // 0..63 (row within tile half)
    const int lk = (tid & 3) << 2;      // 0,4,8,12 (k offset)

    const float* Ag = A + (size_t)(bm + lr) * K + lk;
    const float* Bg = B + (size_t)(bn + lr) * K + lk;
    const size_t Aoff64 = (size_t)64 * K;

    // compute mapping
    const int r = tid >> 4;             // 0..15
    const int c = tid & 15;             // 0..15

    float acc[8][8];
#pragma unroll
    for (int i = 0; i < 8; ++i)
#pragma unroll
        for (int j = 0; j < 8; ++j) acc[i][j] = 0.f;

    for (int kt = 0; kt < K; kt += 16) {
        const float4 a0 = *(const float4*)(Ag + kt);
        const float4 a1 = *(const float4*)(Ag + Aoff64 + kt);
        const float4 b0 = *(const float4*)(Bg + kt);
        const float4 b1 = *(const float4*)(Bg + Aoff64 + kt);

        __syncthreads();   // prior iteration's compute done before overwrite

        As[lk + 0][lr] = a0.x; As[lk + 1][lr] = a0.y;
        As[lk + 2][lr] = a0.z; As[lk + 3][lr] = a0.w;
        As[lk + 0][lr + 64] = a1.x; As[lk + 1][lr + 64] = a1.y;
        As[lk + 2][lr + 64] = a1.z; As[lk + 3][lr + 64] = a1.w;

        Bs[lk + 0][lr] = b0.x; Bs[lk + 1][lr] = b0.y;
        Bs[lk + 2][lr] = b0.z; Bs[lk + 3][lr] = b0.w;
        Bs[lk + 0][lr + 64] = b1.x; Bs[lk + 1][lr + 64] = b1.y;
        Bs[lk + 2][lr + 64] = b1.z; Bs[lk + 3][lr + 64] = b1.w;

        __syncthreads();

#pragma unroll
        for (int kk = 0; kk < 16; ++kk) {
            const float4 fa0 = *(const float4*)&As[kk][r * 4];
            const float4 fa1 = *(const float4*)&As[kk][64 + r * 4];
            const float4 fb0 = *(const float4*)&Bs[kk][c * 4];
            const float4 fb1 = *(const float4*)&Bs[kk][64 + c * 4];
            const float ra[8] = {fa0.x, fa0.y, fa0.z, fa0.w,
                                 fa1.x, fa1.y, fa1.z, fa1.w};
            const float rb[8] = {fb0.x, fb0.y, fb0.z, fb0.w,
                                 fb1.x, fb1.y, fb1.z, fb1.w};
#pragma unroll
            for (int i = 0; i < 8; ++i)
#pragma unroll
                for (int j = 0; j < 8; ++j)
                    acc[i][j] += ra[i] * rb[j];
        }
    }

    // epilogue
    float bias0[4], bias1[4];
    if (BIAS) {
#pragma unroll
        for (int j = 0; j < 4; ++j) {
            bias0[j] = bias[bn + c * 4 + j];
            bias1[j] = bias[bn + 64 + c * 4 + j];
        }
    }

#pragma unroll
    for (int i = 0; i < 8; ++i) {
        const int row = bm + ((i < 4) ? (r * 4 + i) : (64 + r * 4 + (i - 4)));
        float4 v0, v1;
        v0.x = acc[i][0]; v0.y = acc[i][1]; v0.z = acc[i][2]; v0.w = acc[i][3];
        v1.x = acc[i][4]; v1.y = acc[i][5]; v1.z = acc[i][6]; v1.w = acc[i][7];
        if (BIAS) {
            v0.x += bias0[0]; v0.y += bias0[1]; v0.z += bias0[2]; v0.w += bias0[3];
            v1.x += bias1[0]; v1.y += bias1[1]; v1.z += bias1[2]; v1.w += bias1[3];
        }
        float* crow = C + (size_t)row * N + bn;
        *(float4*)(crow + c * 4)      = v0;
        *(float4*)(crow + 64 + c * 4) = v1;
    }
}

// ---------------------------------------------------------------------------
// Row L2-normalization in place. One CTA (256 threads) per row of [B, 1024].
// ---------------------------------------------------------------------------
__global__ void __launch_bounds__(256)
norm_rows(float* __restrict__ P)
{
    const int row = blockIdx.x;
    const int tid = threadIdx.x;
    float* p = P + (size_t)row * FDIM + tid * 4;

    float4 v = *(float4*)p;
    float ss = v.x * v.x + v.y * v.y + v.z * v.z + v.w * v.w;

    __shared__ float red[256];
    red[tid] = ss;
    __syncthreads();
#pragma unroll
    for (int off = 128; off > 0; off >>= 1) {
        if (tid < off) red[tid] += red[tid + off];
        __syncthreads();
    }
    const float inv = 1.0f / fmaxf(sqrtf(red[0]), 1e-12f);
    v.x *= inv; v.y *= inv; v.z *= inv; v.w *= inv;
    *(float4*)p = v;
}

// ---------------------------------------------------------------------------
// Per-row softmax(sim * INV_T) + argmax. One CTA (256 threads) per row.
// Pass 1: online (max, Z, argmax). Pass 2: write normalized activations
// (second read is L2-resident). best_idx written as float.
// ---------------------------------------------------------------------------
__global__ void __launch_bounds__(256)
softmax_row(const float* __restrict__ S,
            float* __restrict__ act,
            float* __restrict__ bidx)
{
    const int row = blockIdx.x;
    const int tid = threadIdx.x;
    const float* s = S + (size_t)row * NCONCEPT;

    float m = -INFINITY;
    float Z = 0.f;
    int   bi = 0;

    for (int j = tid; j < NCONCEPT; j += 256) {
        const float v = s[j];
        if (v > m) {
            Z = Z * __expf((m - v) * INV_T) + 1.0f;
            m = v;
            bi = j;
        } else {
            Z += __expf((v - m) * INV_T);
        }
    }

    __shared__ float sm[256];
    __shared__ float sz[256];
    __shared__ int   si[256];
    sm[tid] = m; sz[tid] = Z; si[tid] = bi;
    __syncthreads();

#pragma unroll
    for (int off = 128; off > 0; off >>= 1) {
        if (tid < off) {
            const float m1 = sm[tid],       z1 = sz[tid];
            const float m2 = sm[tid + off], z2 = sz[tid + off];
            const int   i1 = si[tid],       i2 = si[tid + off];
            if (m2 > m1 || (m2 == m1 && i2 < i1)) {
                sm[tid] = m2;
                sz[tid] = z2 + z1 * __expf((m1 - m2) * INV_T);
                si[tid] = i2;
            } else {
                sz[tid] = z1 + z2 * __expf((m2 - m1) * INV_T);
            }
        }
        __syncthreads();
    }

    const float M    = sm[0];
    const float invZ = 1.0f / sz[0];
    float* a = act + (size_t)row * NCONCEPT;
    for (int j = tid; j < NCONCEPT; j += 256)
        a[j] = __expf((s[j] - M) * INV_T) * invZ;

    if (tid == 0) bidx[row] = (float)si[0];
}

// ---------------------------------------------------------------------------
extern "C" void kernel_launch(void* const* d_in, const int* in_sizes, int n_in,
                              void* d_out, int out_size)
{
    const float* features   = (const float*)d_in[0];  // [1024, 1024]
    const float* W          = (const float*)d_in[1];  // [1024, 1024]
    const float* b          = (const float*)d_in[2];  // [1024]
    const float* prototypes = (const float*)d_in[3];  // [32768, 1024]

    float* out  = (float*)d_out;
    float* act  = out;                                   // [1024, 32768]
    float* bidx = out + (size_t)BATCH * NCONCEPT;        // [1024] as float

    float *pP = nullptr, *pS = nullptr;
    cudaGetSymbolAddress((void**)&pP, g_P);
    cudaGetSymbolAddress((void**)&pS, g_S);

    // 1) projection: P = features @ W^T + b   [1024, 1024]
    sgemm128_nt<true><<<dim3(FDIM / 128, BATCH / 128), 256>>>(
        features, W, b, pP, BATCH, FDIM, FDIM);

    // 2) L2-normalize rows of P (in place)
    norm_rows<<<BATCH, 256>>>(pP);

    // 3) similarities: S = Pn @ prototypes^T   [1024, 32768]
    sgemm128_nt<false><<<dim3(NCONCEPT / 128, BATCH / 128), 256>>>(
        pP, prototypes, nullptr, pS, BATCH, NCONCEPT, FDIM);

    // 4) per-row softmax(S/T) + argmax
    softmax_row<<<BATCH, 256>>>(pS, act, bidx);
}

// round 3
// speedup vs baseline: 2.1785x; 2.1785x over previous
#include <cuda_runtime.h>
#include <cuda_bf16.h>
#include <math.h>
#include <stdint.h>

// Problem constants
#define BATCH     1024
#define FDIM      1024
#define NCONCEPT  32768
#define INV_T     10.0f   // 1 / 0.1

#define TILE_B    16384          // one 128x64-bf16 swizzled tile (128 rows * 128 B)
#define KCHUNKS   16             // 1024 / 64
#define STAGE_B   (4 * TILE_B)   // Ahi, Alo, Bhi, Blo per stage = 64 KB
#define NSTAGES   3
#define SMEM_TOTAL (1024 + NSTAGES * STAGE_B)

// ---------------- scratch (device globals; no allocation allowed) ----------
__device__ float g_P[BATCH * FDIM];                          // projected (then normalized)
__device__ float g_S[(size_t)BATCH * NCONCEPT];              // similarities (134 MB)
__device__ __align__(256) char g_Ahi[(size_t)BATCH * FDIM * 2];       // 2 MB
__device__ __align__(256) char g_Alo[(size_t)BATCH * FDIM * 2];
__device__ __align__(256) char g_Bhi[(size_t)NCONCEPT * FDIM * 2];    // 64 MB
__device__ __align__(256) char g_Blo[(size_t)NCONCEPT * FDIM * 2];

// ---------------------------------------------------------------------------
// PTX helpers (baseline ISA only — no 'a'-suffix features)
// ---------------------------------------------------------------------------
__device__ __forceinline__ uint32_t sm_u32(const void* p) {
    uint32_t a;
    asm("{ .reg .u64 t; cvta.to.shared.u64 t, %1; cvt.u32.u64 %0, t; }"
        : "=r"(a) : "l"(p));
    return a;
}

__device__ __forceinline__ void mbar_wait(uint32_t addr, int phase) {
    asm volatile(
        "{\n\t.reg .pred P;\n\t"
        "WL_%=:\n\t"
        "mbarrier.try_wait.parity.acquire.cta.shared::cta.b64 P, [%0], %1, 0x989680;\n\t"
        "@P bra.uni WD_%=;\n\t"
        "bra.uni WL_%=;\n\t"
        "WD_%=:\n\t}"
        :: "r"(addr), "r"((uint32_t)phase) : "memory");
}

#define LDSM4(R, addr) \
    asm volatile("ldmatrix.sync.aligned.m8n8.x4.shared.b16 {%0,%1,%2,%3}, [%4];" \
        : "=r"((R)[0]), "=r"((R)[1]), "=r"((R)[2]), "=r"((R)[3]) : "r"(addr))

#define MMA_BF16(C, A, b0_, b1_) \
    asm volatile("mma.sync.aligned.m16n8k16.row.col.f32.bf16.bf16.f32 " \
        "{%0,%1,%2,%3}, {%4,%5,%6,%7}, {%8,%9}, {%0,%1,%2,%3};" \
        : "+f"((C)[0]), "+f"((C)[1]), "+f"((C)[2]), "+f"((C)[3]) \
        : "r"((A)[0]), "r"((A)[1]), "r"((A)[2]), "r"((A)[3]), "r"(b0_), "r"(b1_))

#define BULK_LOAD(dst, src, bar) \
    asm volatile("cp.async.bulk.shared::cluster.global.mbarrier::complete_tx::bytes " \
        "[%0], [%1], %2, [%3];" \
        :: "r"(dst), "l"(src), "r"((uint32_t)TILE_B), "r"(bar) : "memory")

// ---------------------------------------------------------------------------
// fp32 SGEMM (projection only): C[m,n] = sum_k A[m,k]*B[n,k] + bias[n]
// ---------------------------------------------------------------------------
template <bool BIAS>
__global__ void __launch_bounds__(256, 2)
sgemm128_nt(const float* __restrict__ A, const float* __restrict__ B,
            const float* __restrict__ bias, float* __restrict__ C,
            int M, int N, int K)
{
    __shared__ __align__(16) float As[16][132];
    __shared__ __align__(16) float Bs[16][132];

    const int tid = threadIdx.x;
    const int bm  = blockIdx.y * 128;
    const int bn  = blockIdx.x * 128;
    const int lr = tid >> 2;
    const int lk = (tid & 3) << 2;

    const float* Ag = A + (size_t)(bm + lr) * K + lk;
    const float* Bg = B + (size_t)(bn + lr) * K + lk;
    const size_t Aoff64 = (size_t)64 * K;

    const int r = tid >> 4;
    const int c = tid & 15;

    float acc[8][8];
#pragma unroll
    for (int i = 0; i < 8; ++i)
#pragma unroll
        for (int j = 0; j < 8; ++j) acc[i][j] = 0.f;

    for (int kt = 0; kt < K; kt += 16) {
        const float4 a0 = *(const float4*)(Ag + kt);
        const float4 a1 = *(const float4*)(Ag + Aoff64 + kt);
        const float4 b0 = *(const float4*)(Bg + kt);
        const float4 b1 = *(const float4*)(Bg + Aoff64 + kt);

        __syncthreads();
        As[lk + 0][lr] = a0.x; As[lk + 1][lr] = a0.y;
        As[lk + 2][lr] = a0.z; As[lk + 3][lr] = a0.w;
        As[lk + 0][lr + 64] = a1.x; As[lk + 1][lr + 64] = a1.y;
        As[lk + 2][lr + 64] = a1.z; As[lk + 3][lr + 64] = a1.w;
        Bs[lk + 0][lr] = b0.x; Bs[lk + 1][lr] = b0.y;
        Bs[lk + 2][lr] = b0.z; Bs[lk + 3][lr] = b0.w;
        Bs[lk + 0][lr + 64] = b1.x; Bs[lk + 1][lr + 64] = b1.y;
        Bs[lk + 2][lr + 64] = b1.z; Bs[lk + 3][lr + 64] = b1.w;
        __syncthreads();

#pragma unroll
        for (int kk = 0; kk < 16; ++kk) {
            const float4 fa0 = *(const float4*)&As[kk][r * 4];
            const float4 fa1 = *(const float4*)&As[kk][64 + r * 4];
            const float4 fb0 = *(const float4*)&Bs[kk][c * 4];
            const float4 fb1 = *(const float4*)&Bs[kk][64 + c * 4];
            const float ra[8] = {fa0.x, fa0.y, fa0.z, fa0.w, fa1.x, fa1.y, fa1.z, fa1.w};
            const float rb[8] = {fb0.x, fb0.y, fb0.z, fb0.w, fb1.x, fb1.y, fb1.z, fb1.w};
#pragma unroll
            for (int i = 0; i < 8; ++i)
#pragma unroll
                for (int j = 0; j < 8; ++j)
                    acc[i][j] += ra[i] * rb[j];
        }
    }

    float bias0[4], bias1[4];
    if (BIAS) {
#pragma unroll
        for (int j = 0; j < 4; ++j) {
            bias0[j] = bias[bn + c * 4 + j];
            bias1[j] = bias[bn + 64 + c * 4 + j];
        }
    }
#pragma unroll
    for (int i = 0; i < 8; ++i) {
        const int row = bm + ((i < 4) ? (r * 4 + i) : (64 + r * 4 + (i - 4)));
        float4 v0, v1;
        v0.x = acc[i][0]; v0.y = acc[i][1]; v0.z = acc[i][2]; v0.w = acc[i][3];
        v1.x = acc[i][4]; v1.y = acc[i][5]; v1.z = acc[i][6]; v1.w = acc[i][7];
        if (BIAS) {
            v0.x += bias0[0]; v0.y += bias0[1]; v0.z += bias0[2]; v0.w += bias0[3];
            v1.x += bias1[0]; v1.y += bias1[1]; v1.z += bias1[2]; v1.w += bias1[3];
        }
        float* crow = C + (size_t)row * N + bn;
        *(float4*)(crow + c * 4)      = v0;
        *(float4*)(crow + 64 + c * 4) = v1;
    }
}

// ---------------------------------------------------------------------------
// Row L2-normalization in place. One CTA (256 threads) per row of [B, 1024].
// ---------------------------------------------------------------------------
__global__ void __launch_bounds__(256)
norm_rows(float* __restrict__ P)
{
    const int row = blockIdx.x;
    const int tid = threadIdx.x;
    float* p = P + (size_t)row * FDIM + tid * 4;

    float4 v = *(float4*)p;
    float ss = v.x * v.x + v.y * v.y + v.z * v.z + v.w * v.w;

    __shared__ float red[256];
    red[tid] = ss;
    __syncthreads();
#pragma unroll
    for (int off = 128; off > 0; off >>= 1) {
        if (tid < off) red[tid] += red[tid + off];
        __syncthreads();
    }
    const float inv = 1.0f / fmaxf(sqrtf(red[0]), 1e-12f);
    v.x *= inv; v.y *= inv; v.z *= inv; v.w *= inv;
    *(float4*)p = v;
}

// ---------------------------------------------------------------------------
// Split fp32 -> (bf16 hi, bf16 lo) into pre-swizzled 128x64 tiles.
// tile_idx = (row>>7)*16 + (k>>6); within tile: SW128 swizzle of
// (row&127)*128 + (k&63)*2   (== off ^ ((row&7)<<4) for these offsets).
// ---------------------------------------------------------------------------
__global__ void __launch_bounds__(256)
convert_split(const float4* __restrict__ src, char* __restrict__ hi, char* __restrict__ lo)
{
    const size_t i4 = (size_t)blockIdx.x * 256 + threadIdx.x;
    const int row = (int)(i4 >> 8);          // 256 float4 per 1024-wide row
    const int k   = ((int)i4 & 255) * 4;
    const float4 v = src[i4];

    unsigned short h[4], l[4];
    const float x[4] = {v.x, v.y, v.z, v.w};
#pragma unroll
    for (int j = 0; j < 4; ++j) {
        __nv_bfloat16 hb = __float2bfloat16(x[j]);
        float r = x[j] - __bfloat162float(hb);
        __nv_bfloat16 lb = __float2bfloat16(r);
        h[j] = __bfloat16_as_ushort(hb);
        l[j] = __bfloat16_as_ushort(lb);
    }

    const int tile = (row >> 7) * 16 + (k >> 6);
    uint32_t off = (uint32_t)((row & 127) * 128 + (k & 63) * 2);
    off ^= (off >> 3) & 0x70;

    uint2 ph, pl;
    ph.x = (uint32_t)h[0] | ((uint32_t)h[1] << 16);
    ph.y = (uint32_t)h[2] | ((uint32_t)h[3] << 16);
    pl.x = (uint32_t)l[0] | ((uint32_t)l[1] << 16);
    pl.y = (uint32_t)l[2] | ((uint32_t)l[3] << 16);
    *(uint2*)(hi + (size_t)tile * TILE_B + off) = ph;
    *(uint2*)(lo + (size_t)tile * TILE_B + off) = pl;
}

// ---------------------------------------------------------------------------
// Similarity GEMM via warp-level bf16 mma.sync (split-bf16, 3 terms ~= fp32):
//   S[m,n] = sum_k A[m,k]*B[n,k],  A = Ahi+Alo, B = Bhi+Blo (lo*lo dropped)
// CTA tile 128x128 (8 warps, 4M x 2N, warp tile 32x64). K chunks of 64.
// cp.async.bulk (4 x 16KB per stage) + mbarrier expect_tx, 3-stage pipeline.
// SMEM tiles are SW128-swizzled in GMEM already, so bulk copies are linear.
// ---------------------------------------------------------------------------
__global__ void __launch_bounds__(256, 1)
sim_mma(const char* __restrict__ Ahi, const char* __restrict__ Alo,
        const char* __restrict__ Bhi, const char* __restrict__ Blo,
        float* __restrict__ S)
{
    extern __shared__ char smem_raw[];
    const uint32_t sbase = sm_u32(smem_raw);
    const uint32_t mbar0 = sbase;                          // 3 x 8B mbarriers
    const uint32_t data0 = (sbase + 24u + 1023u) & ~1023u; // 1024-aligned stages

    const int tid = threadIdx.x;
    const int w = tid >> 5, l = tid & 31;
    const int wm = w & 3;         // 0..3  (M block of 32)
    const int wn = w >> 2;        // 0..1  (N block of 64)
    const int mb = blockIdx.x;    // 0..7
    const int nb = blockIdx.y;    // 0..255

    if (tid == 0) {
#pragma unroll
        for (int s = 0; s < NSTAGES; ++s)
            asm volatile("mbarrier.init.shared.b64 [%0], 1;" :: "r"(mbar0 + s * 8) : "memory");
    }
    __syncthreads();

    // per-thread ldmatrix addressing constants
    const int rowA  = wm * 32 + (l & 15);          // A: lanes 0-15 rows, 16-31 k-half
    const uint32_t hA = (uint32_t)(l >> 4) << 4;   // 0 / 16 bytes
    const int rowB0 = wn * 64 + (l & 7) + ((l & 16) >> 1);  // B: 0-7 n, 8-15 k-half, 16.. n+8
    const uint32_t hB = (uint32_t)(l & 8) << 1;    // 0 / 16 bytes
    const uint32_t swz = (uint32_t)(l & 7) << 4;

    float acc[2][8][4];
#pragma unroll
    for (int i = 0; i < 2; ++i)
#pragma unroll
        for (int j = 0; j < 8; ++j)
#pragma unroll
            for (int q = 0; q < 4; ++q) acc[i][j][q] = 0.f;

    auto issue = [&](int kc, int s) {
        const uint32_t d = data0 + s * STAGE_B;
        const uint32_t bar = mbar0 + s * 8;
        const size_t aoff = ((size_t)mb * KCHUNKS + kc) * TILE_B;
        const size_t boff = ((size_t)nb * KCHUNKS + kc) * TILE_B;
        asm volatile("mbarrier.arrive.expect_tx.shared.b64 _, [%0], %1;"
                     :: "r"(bar), "r"((uint32_t)STAGE_B) : "memory");
        BULK_LOAD(d,                 Ahi + aoff, bar);
        BULK_LOAD(d + 1 * TILE_B,    Alo + aoff, bar);
        BULK_LOAD(d + 2 * TILE_B,    Bhi + boff, bar);
        BULK_LOAD(d + 3 * TILE_B,    Blo + boff, bar);
    };

    if (tid == 0) { issue(0, 0); issue(1, 1); }

    int ph[NSTAGES] = {0, 0, 0};

    for (int kc = 0; kc < KCHUNKS; ++kc) {
        const int s = kc % NSTAGES;
        mbar_wait(mbar0 + s * 8, ph[s]);
        ph[s] ^= 1;
        __syncthreads();   // all warps done computing chunk kc-1 -> its stage reusable
        if (tid == 0 && kc + 2 < KCHUNKS) issue(kc + 2, (kc + 2) % NSTAGES);

        const uint32_t aHb = data0 + s * STAGE_B;
        const uint32_t aLb = aHb + 1 * TILE_B;
        const uint32_t bHb = aHb + 2 * TILE_B;
        const uint32_t bLb = aHb + 3 * TILE_B;

#pragma unroll
        for (int ks = 0; ks < 4; ++ks) {
            uint32_t ah[2][4], al[2][4];
#pragma unroll
            for (int mi = 0; mi < 2; ++mi) {
                const uint32_t pa =
                    ((uint32_t)((rowA + mi * 16) * 128) + (uint32_t)(ks * 32) + hA) ^ swz;
                LDSM4(ah[mi], aHb + pa);
                LDSM4(al[mi], aLb + pa);
            }
#pragma unroll
            for (int nk = 0; nk < 4; ++nk) {
                const uint32_t pb =
                    ((uint32_t)((rowB0 + nk * 16) * 128) + (uint32_t)(ks * 32) + hB) ^ swz;
                uint32_t bh[4], bl[4];
                LDSM4(bh, bHb + pb);
                LDSM4(bl, bLb + pb);
#pragma unroll
                for (int mi = 0; mi < 2; ++mi) {
                    MMA_BF16(acc[mi][nk * 2 + 0], ah[mi], bh[0], bh[1]);
                    MMA_BF16(acc[mi][nk * 2 + 0], ah[mi], bl[0], bl[1]);
                    MMA_BF16(acc[mi][nk * 2 + 0], al[mi], bh[0], bh[1]);
                    MMA_BF16(acc[mi][nk * 2 + 1], ah[mi], bh[2], bh[3]);
                    MMA_BF16(acc[mi][nk * 2 + 1], ah[mi], bl[2], bl[3]);
                    MMA_BF16(acc[mi][nk * 2 + 1], al[mi], bh[2], bh[3]);
                }
            }
        }
    }

    // epilogue: mma accum layout -> S
    const int gm0 = mb * 128 + wm * 32 + (l >> 2);
    const int gn0 = nb * 128 + wn * 64 + (l & 3) * 2;
#pragma unroll
    for (int mi = 0; mi < 2; ++mi) {
#pragma unroll
        for (int nk = 0; nk < 4; ++nk) {
#pragma unroll
            for (int hf = 0; hf < 2; ++hf) {
                const float* a = acc[mi][nk * 2 + hf];
                float* p = S + (size_t)(gm0 + mi * 16) * NCONCEPT + gn0 + nk * 16 + hf * 8;
                float2 v0; v0.x = a[0]; v0.y = a[1];
                float2 v1; v1.x = a[2]; v1.y = a[3];
                *(float2*)p = v0;
                *(float2*)(p + (size_t)8 * NCONCEPT) = v1;
            }
        }
    }
}

// ---------------------------------------------------------------------------
// Per-row softmax(sim * INV_T) + argmax. One CTA (256 threads) per row.
// ---------------------------------------------------------------------------
__global__ void __launch_bounds__(256)
softmax_row(const float* __restrict__ S,
            float* __restrict__ act,
            float* __restrict__ bidx)
{
    const int row = blockIdx.x;
    const int tid = threadIdx.x;
    const float* s = S + (size_t)row * NCONCEPT;

    float m = -INFINITY;
    float Z = 0.f;
    int   bi = 0;

    for (int j = tid; j < NCONCEPT; j += 256) {
        const float v = s[j];
        if (v > m) {
            Z = Z * __expf((m - v) * INV_T) + 1.0f;
            m = v;
            bi = j;
        } else {
            Z += __expf((v - m) * INV_T);
        }
    }

    __shared__ float sm[256];
    __shared__ float sz[256];
    __shared__ int   si[256];
    sm[tid] = m; sz[tid] = Z; si[tid] = bi;
    __syncthreads();

#pragma unroll
    for (int off = 128; off > 0; off >>= 1) {
        if (tid < off) {
            const float m1 = sm[tid],       z1 = sz[tid];
            const float m2 = sm[tid + off], z2 = sz[tid + off];
            const int   i1 = si[tid],       i2 = si[tid + off];
            if (m2 > m1 || (m2 == m1 && i2 < i1)) {
                sm[tid] = m2;
                sz[tid] = z2 + z1 * __expf((m1 - m2) * INV_T);
                si[tid] = i2;
            } else {
                sz[tid] = z1 + z2 * __expf((m2 - m1) * INV_T);
            }
        }
        __syncthreads();
    }

    const float M    = sm[0];
    const float invZ = 1.0f / sz[0];
    float* a = act + (size_t)row * NCONCEPT;
    for (int j = tid; j < NCONCEPT; j += 256)
        a[j] = __expf((s[j] - M) * INV_T) * invZ;

    if (tid == 0) bidx[row] = (float)si[0];
}

// ---------------------------------------------------------------------------
extern "C" void kernel_launch(void* const* d_in, const int* in_sizes, int n_in,
                              void* d_out, int out_size)
{
    const float* features   = (const float*)d_in[0];  // [1024, 1024]
    const float* W          = (const float*)d_in[1];  // [1024, 1024]
    const float* b          = (const float*)d_in[2];  // [1024]
    const float* prototypes = (const float*)d_in[3];  // [32768, 1024]

    float* out  = (float*)d_out;
    float* act  = out;                                   // [1024, 32768]
    float* bidx = out + (size_t)BATCH * NCONCEPT;        // [1024] as float

    float *pP = nullptr, *pS = nullptr;
    char *pAhi = nullptr, *pAlo = nullptr, *pBhi = nullptr, *pBlo = nullptr;
    cudaGetSymbolAddress((void**)&pP, g_P);
    cudaGetSymbolAddress((void**)&pS, g_S);
    cudaGetSymbolAddress((void**)&pAhi, g_Ahi);
    cudaGetSymbolAddress((void**)&pAlo, g_Alo);
    cudaGetSymbolAddress((void**)&pBhi, g_Bhi);
    cudaGetSymbolAddress((void**)&pBlo, g_Blo);

    cudaFuncSetAttribute(sim_mma, cudaFuncAttributeMaxDynamicSharedMemorySize, SMEM_TOTAL);

    // 1) projection: P = features @ W^T + b   [1024, 1024] (fp32)
    sgemm128_nt<true><<<dim3(FDIM / 128, BATCH / 128), 256>>>(
        features, W, b, pP, BATCH, FDIM, FDIM);

    // 2) L2-normalize rows of P (in place)
    norm_rows<<<BATCH, 256>>>(pP);

    // 3) split into bf16 hi/lo, pre-swizzled tiles
    convert_split<<<(BATCH * FDIM / 4) / 256, 256>>>((const float4*)pP, pAhi, pAlo);
    convert_split<<<(NCONCEPT * FDIM / 4) / 256, 256>>>((const float4*)prototypes, pBhi, pBlo);

    // 4) similarities: S = Pn @ prototypes^T  via mma.sync split-bf16
    sim_mma<<<dim3(BATCH / 128, NCONCEPT / 128), 256, SMEM_TOTAL>>>(
        pAhi, pAlo, pBhi, pBlo, pS);

    // 5) per-row softmax(S/T) + argmax
    softmax_row<<<BATCH, 256>>>(pS, act, bidx);
}